// round 4
// baseline (speedup 1.0000x reference)
#include <cuda_runtime.h>
#include <math.h>

#define DMODEL 256
#define BATCH  128
#define NHEAD  4
#define DK     64

// 6 scratch buffers of 128*512*256 floats (2^24 each) = 402 MB total.
#define CHUNK (128ull * 512ull * 256ull)
__device__ float g_scratch[6ull * CHUNK];

// ---------------------------------------------------------------------------
// GEMM: C[M,256] = A[M,256] @ W[256,256] (+bias) (optional relu)
// 64x64 block tile, 256 threads, 4x4 microtile, K-step 16.
// ---------------------------------------------------------------------------
__global__ void gemm256(const float* __restrict__ A, const float* __restrict__ W,
                        const float* __restrict__ bias, float* __restrict__ C,
                        int M, int relu) {
    __shared__ float As[16][68];   // transposed: As[k][m]
    __shared__ float Ws[16][68];   // Ws[k][n]
    const int bm = blockIdx.x * 64;
    const int bn = blockIdx.y * 64;
    const int tid = threadIdx.x;
    const int rg = tid >> 4;       // row group (0..15) -> rows rg*4..rg*4+3
    const int cg = tid & 15;       // col group (0..15) -> cols cg*4..cg*4+3

    float acc[4][4] = {};

    for (int k0 = 0; k0 < 256; k0 += 16) {
        // Load A tile (64 rows x 16 k), store transposed
        {
            int m  = tid >> 2;
            int k4 = (tid & 3) * 4;
            float4 a = make_float4(0.f, 0.f, 0.f, 0.f);
            int row = bm + m;
            if (row < M) a = *(const float4*)(A + (size_t)row * DMODEL + k0 + k4);
            As[k4 + 0][m] = a.x;
            As[k4 + 1][m] = a.y;
            As[k4 + 2][m] = a.z;
            As[k4 + 3][m] = a.w;
        }
        // Load W tile (16 k x 64 n)
        {
            int kk = tid >> 4;
            int c4 = (tid & 15) * 4;
            float4 w = *(const float4*)(W + (size_t)(k0 + kk) * DMODEL + bn + c4);
            *(float4*)&Ws[kk][c4] = w;
        }
        __syncthreads();

        #pragma unroll
        for (int k = 0; k < 16; k++) {
            float a[4], b[4];
            #pragma unroll
            for (int i = 0; i < 4; i++) a[i] = As[k][rg * 4 + i];
            #pragma unroll
            for (int j = 0; j < 4; j++) b[j] = Ws[k][cg * 4 + j];
            #pragma unroll
            for (int i = 0; i < 4; i++)
                #pragma unroll
                for (int j = 0; j < 4; j++)
                    acc[i][j] = fmaf(a[i], b[j], acc[i][j]);
        }
        __syncthreads();
    }

    #pragma unroll
    for (int i = 0; i < 4; i++) {
        int row = bm + rg * 4 + i;
        if (row >= M) continue;
        #pragma unroll
        for (int j = 0; j < 4; j++) {
            int col = bn + cg * 4 + j;
            float v = acc[i][j];
            if (bias) v += bias[col];
            if (relu) v = fmaxf(v, 0.f);
            C[(size_t)row * DMODEL + col] = v;
        }
    }
}

// ---------------------------------------------------------------------------
// Fused residual-add + LayerNorm over D=256. One block (256 thr) per row.
// ---------------------------------------------------------------------------
__global__ void add_ln_kernel(const float* __restrict__ A, const float* __restrict__ R,
                              const float* __restrict__ g, const float* __restrict__ bb,
                              float* __restrict__ O) {
    const int row = blockIdx.x;
    const int t = threadIdx.x;
    const size_t base = (size_t)row * DMODEL;
    float v = A[base + t] + R[base + t];

    __shared__ float red[8];
    __shared__ float s_mu, s_rstd;

    float s = v;
    #pragma unroll
    for (int o = 16; o; o >>= 1) s += __shfl_xor_sync(0xffffffffu, s, o);
    if ((t & 31) == 0) red[t >> 5] = s;
    __syncthreads();
    if (t < 32) {
        float x2 = (t < 8) ? red[t] : 0.f;
        #pragma unroll
        for (int o = 4; o; o >>= 1) x2 += __shfl_xor_sync(0xffffffffu, x2, o);
        if (t == 0) s_mu = x2 * (1.f / 256.f);
    }
    __syncthreads();
    float d = v - s_mu;
    float s2 = d * d;
    #pragma unroll
    for (int o = 16; o; o >>= 1) s2 += __shfl_xor_sync(0xffffffffu, s2, o);
    if ((t & 31) == 0) red[t >> 5] = s2;
    __syncthreads();
    if (t < 32) {
        float x2 = (t < 8) ? red[t] : 0.f;
        #pragma unroll
        for (int o = 4; o; o >>= 1) x2 += __shfl_xor_sync(0xffffffffu, x2, o);
        if (t == 0) s_rstd = rsqrtf(x2 * (1.f / 256.f) + 1e-5f);
    }
    __syncthreads();
    O[base + t] = d * s_rstd * g[t] + bb[t];
}

// ---------------------------------------------------------------------------
// Fused attention for one (b, h, q-tile of 32 rows).
//   scores = (Q K^T)/8 ; p = softmax(scores) ; p *= tanh(attn_w[cat]) ; O = p V
// Dynamic smem: sQ[32*64] + sKV[64*64] + sS[32*512] = 90112 B.
// ---------------------------------------------------------------------------
#define QT 32
#define KT 64
__global__ void attn_kernel(const float* __restrict__ Q, const float* __restrict__ Kmat,
                            const float* __restrict__ V, const float* __restrict__ AW,
                            const int* __restrict__ Kcls, float* __restrict__ O, int S) {
    extern __shared__ float sm[];
    float* sQ  = sm;                 // [QT][64]
    float* sKV = sQ + QT * 64;       // [64][64] (d-major for K, k-major for V)
    float* sS  = sKV + 64 * 64;      // [QT][512]
    __shared__ float tw[6];

    const int b = blockIdx.z, h = blockIdx.y;
    const int q0 = blockIdx.x * QT;
    const int tid = threadIdx.x;

    if (tid < 6) tw[tid] = tanhf(AW[h * 6 + tid]);
    const int Kc = *Kcls;
    const int NK = S - 1;

    // Load Q tile (pre-scaled by 1/sqrt(64))
    for (int i = tid; i < QT * 16; i += 256) {
        int qr = i >> 4, d4 = (i & 15) * 4;
        float4 qv = make_float4(0.f, 0.f, 0.f, 0.f);
        if (q0 + qr < S)
            qv = *(const float4*)(Q + ((size_t)(b * S + q0 + qr)) * DMODEL + h * DK + d4);
        sQ[qr * 64 + d4 + 0] = qv.x * 0.125f;
        sQ[qr * 64 + d4 + 1] = qv.y * 0.125f;
        sQ[qr * 64 + d4 + 2] = qv.z * 0.125f;
        sQ[qr * 64 + d4 + 3] = qv.w * 0.125f;
    }
    __syncthreads();

    const int SP = (S + KT - 1) / KT;     // key tiles (8 for S=501)
    const int qg = tid >> 4;              // q rows qg*2, qg*2+1
    const int kg = tid & 15;              // key/val cols kg*4..+3

    // --- phase 1: scores ---
    for (int t = 0; t < SP; t++) {
        int k0 = t * KT;
        for (int i = tid; i < KT * 16; i += 256) {
            int kr = i & 63, d4 = (i >> 6) * 4;
            float4 kv = make_float4(0.f, 0.f, 0.f, 0.f);
            if (k0 + kr < S)
                kv = *(const float4*)(Kmat + ((size_t)(b * S + k0 + kr)) * DMODEL + h * DK + d4);
            sKV[(d4 + 0) * 64 + kr] = kv.x;
            sKV[(d4 + 1) * 64 + kr] = kv.y;
            sKV[(d4 + 2) * 64 + kr] = kv.z;
            sKV[(d4 + 3) * 64 + kr] = kv.w;
        }
        __syncthreads();

        float acc[2][4] = {};
        #pragma unroll 8
        for (int d = 0; d < 64; d++) {
            float a0 = sQ[(qg * 2) * 64 + d];
            float a1 = sQ[(qg * 2 + 1) * 64 + d];
            #pragma unroll
            for (int j = 0; j < 4; j++) {
                float kv = sKV[d * 64 + kg * 4 + j];
                acc[0][j] = fmaf(a0, kv, acc[0][j]);
                acc[1][j] = fmaf(a1, kv, acc[1][j]);
            }
        }
        #pragma unroll
        for (int i = 0; i < 2; i++)
            #pragma unroll
            for (int j = 0; j < 4; j++) {
                int kc = k0 + kg * 4 + j;
                sS[(qg * 2 + i) * 512 + kc] = (kc < S) ? acc[i][j] : -1e30f;
            }
        __syncthreads();
    }

    // --- phase 2: softmax + tanh gate ---
    const int warp = tid >> 5, lane = tid & 31;
    const int SPAD = SP * KT;
    for (int r = warp; r < QT; r += 8) {
        int qglob = q0 + r;
        if (qglob >= S) continue;
        float m = -1e30f;
        for (int c = lane; c < SPAD; c += 32) m = fmaxf(m, sS[r * 512 + c]);
        #pragma unroll
        for (int o = 16; o; o >>= 1) m = fmaxf(m, __shfl_xor_sync(0xffffffffu, m, o));
        float sum = 0.f;
        for (int c = lane; c < SPAD; c += 32) {
            float e = __expf(sS[r * 512 + c] - m);
            sS[r * 512 + c] = e;
            sum += e;
        }
        #pragma unroll
        for (int o = 16; o; o >>= 1) sum += __shfl_xor_sync(0xffffffffu, sum, o);
        float inv = 1.f / sum;
        for (int c = lane; c < SPAD; c += 32) {
            float gte = 0.f;
            if (c < S) {
                int cat;
                if (qglob == NK)      cat = (c == NK) ? 5 : 4;
                else if (c == NK)     cat = 3;
                else if (qglob == c)  cat = 0;
                else if (qglob / Kc == c / Kc) cat = 1;
                else                  cat = 2;
                gte = tw[cat];
            }
            sS[r * 512 + c] *= gte * inv;
        }
    }
    __syncthreads();

    // --- phase 3: O = P @ V ---
    float oacc[2][4] = {};
    for (int t = 0; t < SP; t++) {
        int k0 = t * KT;
        for (int i = tid; i < KT * 16; i += 256) {
            int kr = i >> 4, n4 = (i & 15) * 4;
            float4 vv = make_float4(0.f, 0.f, 0.f, 0.f);
            if (k0 + kr < S)
                vv = *(const float4*)(V + ((size_t)(b * S + k0 + kr)) * DMODEL + h * DK + n4);
            *(float4*)&sKV[kr * 64 + n4] = vv;
        }
        __syncthreads();

        #pragma unroll 8
        for (int k = 0; k < KT; k++) {
            float p0 = sS[(qg * 2) * 512 + k0 + k];
            float p1 = sS[(qg * 2 + 1) * 512 + k0 + k];
            #pragma unroll
            for (int j = 0; j < 4; j++) {
                float vv = sKV[k * 64 + kg * 4 + j];
                oacc[0][j] = fmaf(p0, vv, oacc[0][j]);
                oacc[1][j] = fmaf(p1, vv, oacc[1][j]);
            }
        }
        __syncthreads();
    }

    #pragma unroll
    for (int i = 0; i < 2; i++) {
        int qglob = q0 + qg * 2 + i;
        if (qglob >= S) continue;
        #pragma unroll
        for (int j = 0; j < 4; j++)
            O[((size_t)(b * S + qglob)) * DMODEL + h * DK + kg * 4 + j] = oacc[i][j];
    }
}

// ---------------------------------------------------------------------------
extern "C" void kernel_launch(void* const* d_in, const int* in_sizes, int n_in,
                              void* d_out, int out_size) {
    const float* samples  = (const float*)d_in[0];
    const float* Wq       = (const float*)d_in[1];
    const float* Wk       = (const float*)d_in[2];
    const float* Wv       = (const float*)d_in[3];
    const float* attn_w   = (const float*)d_in[4];
    const float* mha_fc_w = (const float*)d_in[5];
    const float* mha_fc_b = (const float*)d_in[6];
    const float* mha_ln_g = (const float*)d_in[7];
    const float* mha_ln_b = (const float*)d_in[8];
    const float* d_fc1_w  = (const float*)d_in[9];
    const float* d_fc1_b  = (const float*)d_in[10];
    const float* d_fc2_w  = (const float*)d_in[11];
    const float* d_fc2_b  = (const float*)d_in[12];
    const float* d_ln_g   = (const float*)d_in[13];
    const float* d_ln_b   = (const float*)d_in[14];
    const float* out_fc_w = (const float*)d_in[15];
    const float* out_fc_b = (const float*)d_in[16];
    const float* out_ln_g = (const float*)d_in[17];
    const float* out_ln_b = (const float*)d_in[18];
    const int*   Kptr     = (const int*)d_in[20];

    const int S = in_sizes[0] / (BATCH * DMODEL);
    const int M = BATCH * S;

    float* base = nullptr;
    cudaGetSymbolAddress((void**)&base, g_scratch);
    float* x  = base + 0 * CHUNK;
    float* q  = base + 1 * CHUNK;
    float* k  = base + 2 * CHUNK;
    float* v  = base + 3 * CHUNK;
    float* ao = base + 4 * CHUNK;
    float* t1 = base + 5 * CHUNK;
    float* hb = q;   // FFN hidden reuses q buffer (dead after attention)

    const int ATTN_SMEM = (QT * 64 + 64 * 64 + QT * 512) * 4;  // 90112
    cudaFuncSetAttribute(attn_kernel, cudaFuncAttributeMaxDynamicSharedMemorySize, ATTN_SMEM);

    dim3 gg((M + 63) / 64, 4);
    dim3 ga((S + QT - 1) / QT, NHEAD, BATCH);

    for (int l = 0; l < 2; l++) {
        const float* xin = (l == 0) ? samples : x;
        const size_t wo = (size_t)l * 65536;
        gemm256<<<gg, 256>>>(xin, Wq + wo, nullptr, q, M, 0);
        gemm256<<<gg, 256>>>(xin, Wk + wo, nullptr, k, M, 0);
        gemm256<<<gg, 256>>>(xin, Wv + wo, nullptr, v, M, 0);
        attn_kernel<<<ga, 256, ATTN_SMEM>>>(q, k, v, attn_w + l * 24, Kptr, ao, S);
        gemm256<<<gg, 256>>>(ao, mha_fc_w + wo, mha_fc_b + l * 256, t1, M, 0);
        add_ln_kernel<<<M, 256>>>(t1, xin, mha_ln_g + l * 256, mha_ln_b + l * 256, x);
        gemm256<<<gg, 256>>>(x, d_fc1_w + wo, d_fc1_b + l * 256, hb, M, 1);
        gemm256<<<gg, 256>>>(hb, d_fc2_w + wo, d_fc2_b + l * 256, t1, M, 0);
        add_ln_kernel<<<M, 256>>>(t1, x, d_ln_g + l * 256, d_ln_b + l * 256, x);
    }
    gemm256<<<gg, 256>>>(x, out_fc_w, out_fc_b, t1, M, 0);
    add_ln_kernel<<<M, 256>>>(t1, samples, out_ln_g, out_ln_b, (float*)d_out);
}

// round 7
// speedup vs baseline: 1.2849x; 1.2849x over previous
#include <cuda_runtime.h>
#include <cuda_bf16.h>
#include <math.h>
#include <stdint.h>

#define DMODEL 256
#define BATCH  128
#define NHEAD  4
#define DK     64

// scratch: x, q, k, v, ao  (5 chunks)
#define CHUNK (128ull * 512ull * 256ull)
__device__ float g_scratch[5ull * CHUNK];
// 13 weight matrices, transposed + split: per matrix 131072 bf16:
//   hi[n*256+k] at +0 (65536), lo at +65536.
__device__ __nv_bfloat16 g_wsplit[13ull * 131072ull];

// ---------------------------------------------------------------------------
__device__ __forceinline__ void mma16816(float* c,
                                         uint32_t a0, uint32_t a1, uint32_t a2, uint32_t a3,
                                         uint32_t b0, uint32_t b1) {
    asm volatile(
        "mma.sync.aligned.m16n8k16.row.col.f32.bf16.bf16.f32 "
        "{%0,%1,%2,%3},{%4,%5,%6,%7},{%8,%9},{%0,%1,%2,%3};"
        : "+f"(c[0]), "+f"(c[1]), "+f"(c[2]), "+f"(c[3])
        : "r"(a0), "r"(a1), "r"(a2), "r"(a3), "r"(b0), "r"(b1));
}

// ---------------------------------------------------------------------------
// Weight prep: W[256k,256n] fp32 -> hi/lo bf16 images [n][k] (col-major B).
// ---------------------------------------------------------------------------
struct WP { const float* p[13]; };

__global__ void prep_w(WP wp, __nv_bfloat16* dst) {
    const int mid = blockIdx.y;
    const float* W = wp.p[mid];
    __nv_bfloat16* hi = dst + (size_t)mid * 131072;
    __nv_bfloat16* lo = hi + 65536;
    int idx0 = blockIdx.x * 1024 + threadIdx.x;
    #pragma unroll
    for (int i = 0; i < 4; i++) {
        int idx = idx0 + i * 256;          // linear over W: coalesced read
        int k = idx >> 8, n = idx & 255;
        float x = W[idx];
        __nv_bfloat16 h = __float2bfloat16(x);
        hi[n * 256 + k] = h;
        lo[n * 256 + k] = __float2bfloat16(x - __bfloat162float(h));
    }
}

// ---------------------------------------------------------------------------
// HMMA GEMM: C[M,256] = A[M,256] @ W (+bias)(+relu) or (+bias+resid+LN).
// CTA tile 128x256, 256 threads (8 warps, 2M x 4N), warp tile 64x64.
// 3-pass split bf16: hi*hi + hi*lo + lo*hi, fp32 accum.
// smem: Ahi/Alo [128][264] bf16, Bhi/Blo [256][72] bf16 (per 64-k chunk).
// ---------------------------------------------------------------------------
#define AST 264
#define BST 72
#define GEMM_DYN ((128 * AST * 2 + 256 * BST * 2) * 2)   // 208896 bytes

__global__ __launch_bounds__(256) void gemm_tc(
    const float* __restrict__ A, const __nv_bfloat16* __restrict__ Wsp,
    const float* __restrict__ bias, const float* __restrict__ resid,
    const float* __restrict__ lng, const float* __restrict__ lnb,
    float* __restrict__ C, int relu)
{
    extern __shared__ __nv_bfloat16 dsm[];
    __nv_bfloat16* sAhi = dsm;                    // 128*264
    __nv_bfloat16* sAlo = sAhi + 128 * AST;
    __nv_bfloat16* sBhi = sAlo + 128 * AST;       // 256*72
    __nv_bfloat16* sBlo = sBhi + 256 * BST;

    __shared__ float s_bias[256], s_g[256], s_b[256];
    __shared__ float s_sum[128], s_ssq[128];

    const int tid = threadIdx.x;
    const int wid = tid >> 5, lane = tid & 31;
    const int wm = wid >> 2, wn = wid & 3;        // 2 x 4 warp grid
    const int lq = lane >> 2, lr = lane & 3;
    const int bm = blockIdx.x * 128;

    s_bias[tid] = bias ? bias[tid] : 0.f;
    if (resid) { s_g[tid] = lng[tid]; s_b[tid] = lnb[tid]; }
    if (tid < 128) { s_sum[tid] = 0.f; s_ssq[tid] = 0.f; }

    // ---- load + split A tile [128 x 256] ----
    #pragma unroll
    for (int i = 0; i < 32; i++) {
        int it = tid + i * 256;                   // 8192 float4s
        int m = it >> 6, k4 = (it & 63) << 2;
        float4 a = *(const float4*)(A + (size_t)(bm + m) * 256 + k4);
        float h0 = __bfloat162float(__float2bfloat16(a.x));
        float h1 = __bfloat162float(__float2bfloat16(a.y));
        float h2 = __bfloat162float(__float2bfloat16(a.z));
        float h3 = __bfloat162float(__float2bfloat16(a.w));
        __nv_bfloat162 hA = __floats2bfloat162_rn(a.x, a.y);
        __nv_bfloat162 hB = __floats2bfloat162_rn(a.z, a.w);
        __nv_bfloat162 lA = __floats2bfloat162_rn(a.x - h0, a.y - h1);
        __nv_bfloat162 lB = __floats2bfloat162_rn(a.z - h2, a.w - h3);
        uint2 hv = make_uint2(*(uint32_t*)&hA, *(uint32_t*)&hB);
        uint2 lv = make_uint2(*(uint32_t*)&lA, *(uint32_t*)&lB);
        *(uint2*)(sAhi + m * AST + k4) = hv;
        *(uint2*)(sAlo + m * AST + k4) = lv;
    }

    float acc[4][8][4];
    #pragma unroll
    for (int mf = 0; mf < 4; mf++)
        #pragma unroll
        for (int nf = 0; nf < 8; nf++)
            #pragma unroll
            for (int j = 0; j < 4; j++) acc[mf][nf][j] = 0.f;

    const __nv_bfloat16* Whi = Wsp;
    const __nv_bfloat16* Wlo = Wsp + 65536;

    for (int kc = 0; kc < 4; kc++) {
        // ---- load B chunk [256 n x 64 k] hi+lo ----
        __syncthreads();
        #pragma unroll
        for (int i = 0; i < 8; i++) {
            int it = tid + i * 256;               // 2048 uint4 per half
            int n = it >> 3, k8 = (it & 7) << 3;
            *(uint4*)(sBhi + n * BST + k8) = *(const uint4*)(Whi + n * 256 + kc * 64 + k8);
            *(uint4*)(sBlo + n * BST + k8) = *(const uint4*)(Wlo + n * 256 + kc * 64 + k8);
        }
        __syncthreads();

        #pragma unroll
        for (int ks = 0; ks < 4; ks++) {
            const int ka = kc * 64 + ks * 16;
            const int kb = ks * 16;
            #pragma unroll
            for (int pass = 0; pass < 3; pass++) {
                const __nv_bfloat16* Ap = (pass == 2) ? sAlo : sAhi;
                const __nv_bfloat16* Bp = (pass == 1) ? sBlo : sBhi;
                uint32_t af[4][4];
                #pragma unroll
                for (int mf = 0; mf < 4; mf++) {
                    const __nv_bfloat16* ab = Ap + (wm * 64 + mf * 16 + lq) * AST + ka + lr * 2;
                    af[mf][0] = *(const uint32_t*)(ab);
                    af[mf][1] = *(const uint32_t*)(ab + 8 * AST);
                    af[mf][2] = *(const uint32_t*)(ab + 8);
                    af[mf][3] = *(const uint32_t*)(ab + 8 * AST + 8);
                }
                uint32_t bfr[8][2];
                #pragma unroll
                for (int nf = 0; nf < 8; nf++) {
                    const __nv_bfloat16* bb2 = Bp + (wn * 64 + nf * 8 + lq) * BST + kb + lr * 2;
                    bfr[nf][0] = *(const uint32_t*)(bb2);
                    bfr[nf][1] = *(const uint32_t*)(bb2 + 8);
                }
                #pragma unroll
                for (int mf = 0; mf < 4; mf++)
                    #pragma unroll
                    for (int nf = 0; nf < 8; nf++)
                        mma16816(acc[mf][nf], af[mf][0], af[mf][1], af[mf][2], af[mf][3],
                                 bfr[nf][0], bfr[nf][1]);
            }
        }
    }
    __syncthreads();

    // ---- epilogue ----
    // thread's rows: wm*64 + mf*16 + lq (+8); cols: wn*64 + nf*8 + lr*2 (+1)
    if (resid) {
        // bias + residual folded into acc; LN stats; normalize; store.
        #pragma unroll
        for (int mf = 0; mf < 4; mf++) {
            #pragma unroll
            for (int h = 0; h < 2; h++) {
                int r = wm * 64 + mf * 16 + lq + h * 8;
                const float* Rr = resid + (size_t)(bm + r) * 256;
                float ps = 0.f, pq = 0.f;
                #pragma unroll
                for (int nf = 0; nf < 8; nf++) {
                    int c = wn * 64 + nf * 8 + lr * 2;
                    float2 rv = *(const float2*)(Rr + c);
                    float v0 = acc[mf][nf][h * 2 + 0] + s_bias[c] + rv.x;
                    float v1 = acc[mf][nf][h * 2 + 1] + s_bias[c + 1] + rv.y;
                    acc[mf][nf][h * 2 + 0] = v0;
                    acc[mf][nf][h * 2 + 1] = v1;
                    ps += v0 + v1;
                    pq += v0 * v0 + v1 * v1;
                }
                ps += __shfl_xor_sync(0xffffffffu, ps, 1);
                ps += __shfl_xor_sync(0xffffffffu, ps, 2);
                pq += __shfl_xor_sync(0xffffffffu, pq, 1);
                pq += __shfl_xor_sync(0xffffffffu, pq, 2);
                if (lr == 0) {
                    atomicAdd(&s_sum[r], ps);
                    atomicAdd(&s_ssq[r], pq);
                }
            }
        }
        __syncthreads();
        if (tid < 128) {
            float mu = s_sum[tid] * (1.f / 256.f);
            float var = s_ssq[tid] * (1.f / 256.f) - mu * mu;
            s_sum[tid] = mu;
            s_ssq[tid] = rsqrtf(var + 1e-5f);
        }
        __syncthreads();
        #pragma unroll
        for (int mf = 0; mf < 4; mf++) {
            #pragma unroll
            for (int h = 0; h < 2; h++) {
                int r = wm * 64 + mf * 16 + lq + h * 8;
                float mu = s_sum[r], rs = s_ssq[r];
                float* Cr = C + (size_t)(bm + r) * 256;
                #pragma unroll
                for (int nf = 0; nf < 8; nf++) {
                    int c = wn * 64 + nf * 8 + lr * 2;
                    float2 o;
                    o.x = (acc[mf][nf][h * 2 + 0] - mu) * rs * s_g[c] + s_b[c];
                    o.y = (acc[mf][nf][h * 2 + 1] - mu) * rs * s_g[c + 1] + s_b[c + 1];
                    *(float2*)(Cr + c) = o;
                }
            }
        }
    } else {
        #pragma unroll
        for (int mf = 0; mf < 4; mf++) {
            #pragma unroll
            for (int h = 0; h < 2; h++) {
                int r = wm * 64 + mf * 16 + lq + h * 8;
                float* Cr = C + (size_t)(bm + r) * 256;
                #pragma unroll
                for (int nf = 0; nf < 8; nf++) {
                    int c = wn * 64 + nf * 8 + lr * 2;
                    float2 o;
                    o.x = acc[mf][nf][h * 2 + 0] + s_bias[c];
                    o.y = acc[mf][nf][h * 2 + 1] + s_bias[c + 1];
                    if (relu) { o.x = fmaxf(o.x, 0.f); o.y = fmaxf(o.y, 0.f); }
                    *(float2*)(Cr + c) = o;
                }
            }
        }
    }
}

// ---------------------------------------------------------------------------
// Fused attention (unchanged from last passing version)
// ---------------------------------------------------------------------------
#define QT 32
#define KT 64
__global__ void attn_kernel(const float* __restrict__ Q, const float* __restrict__ Kmat,
                            const float* __restrict__ V, const float* __restrict__ AW,
                            const int* __restrict__ Kcls, float* __restrict__ O, int S) {
    extern __shared__ float sm[];
    float* sQ  = sm;
    float* sKV = sQ + QT * 64;
    float* sS  = sKV + 64 * 64;
    __shared__ float tw[6];

    const int b = blockIdx.z, h = blockIdx.y;
    const int q0 = blockIdx.x * QT;
    const int tid = threadIdx.x;

    if (tid < 6) tw[tid] = tanhf(AW[h * 6 + tid]);
    const int Kc = *Kcls;
    const int NK = S - 1;

    for (int i = tid; i < QT * 16; i += 256) {
        int qr = i >> 4, d4 = (i & 15) * 4;
        float4 qv = make_float4(0.f, 0.f, 0.f, 0.f);
        if (q0 + qr < S)
            qv = *(const float4*)(Q + ((size_t)(b * S + q0 + qr)) * DMODEL + h * DK + d4);
        sQ[qr * 64 + d4 + 0] = qv.x * 0.125f;
        sQ[qr * 64 + d4 + 1] = qv.y * 0.125f;
        sQ[qr * 64 + d4 + 2] = qv.z * 0.125f;
        sQ[qr * 64 + d4 + 3] = qv.w * 0.125f;
    }
    __syncthreads();

    const int SP = (S + KT - 1) / KT;
    const int qg = tid >> 4;
    const int kg = tid & 15;

    for (int t = 0; t < SP; t++) {
        int k0 = t * KT;
        for (int i = tid; i < KT * 16; i += 256) {
            int kr = i & 63, d4 = (i >> 6) * 4;
            float4 kv = make_float4(0.f, 0.f, 0.f, 0.f);
            if (k0 + kr < S)
                kv = *(const float4*)(Kmat + ((size_t)(b * S + k0 + kr)) * DMODEL + h * DK + d4);
            sKV[(d4 + 0) * 64 + kr] = kv.x;
            sKV[(d4 + 1) * 64 + kr] = kv.y;
            sKV[(d4 + 2) * 64 + kr] = kv.z;
            sKV[(d4 + 3) * 64 + kr] = kv.w;
        }
        __syncthreads();

        float acc[2][4] = {};
        #pragma unroll 8
        for (int d = 0; d < 64; d++) {
            float a0 = sQ[(qg * 2) * 64 + d];
            float a1 = sQ[(qg * 2 + 1) * 64 + d];
            #pragma unroll
            for (int j = 0; j < 4; j++) {
                float kv = sKV[d * 64 + kg * 4 + j];
                acc[0][j] = fmaf(a0, kv, acc[0][j]);
                acc[1][j] = fmaf(a1, kv, acc[1][j]);
            }
        }
        #pragma unroll
        for (int i = 0; i < 2; i++)
            #pragma unroll
            for (int j = 0; j < 4; j++) {
                int kc2 = k0 + kg * 4 + j;
                sS[(qg * 2 + i) * 512 + kc2] = (kc2 < S) ? acc[i][j] : -1e30f;
            }
        __syncthreads();
    }

    const int warp = tid >> 5, lane = tid & 31;
    const int SPAD = SP * KT;
    for (int r = warp; r < QT; r += 8) {
        int qglob = q0 + r;
        if (qglob >= S) continue;
        float m = -1e30f;
        for (int c = lane; c < SPAD; c += 32) m = fmaxf(m, sS[r * 512 + c]);
        #pragma unroll
        for (int o = 16; o; o >>= 1) m = fmaxf(m, __shfl_xor_sync(0xffffffffu, m, o));
        float sum = 0.f;
        for (int c = lane; c < SPAD; c += 32) {
            float e = __expf(sS[r * 512 + c] - m);
            sS[r * 512 + c] = e;
            sum += e;
        }
        #pragma unroll
        for (int o = 16; o; o >>= 1) sum += __shfl_xor_sync(0xffffffffu, sum, o);
        float inv = 1.f / sum;
        for (int c = lane; c < SPAD; c += 32) {
            float gte = 0.f;
            if (c < S) {
                int cat;
                if (qglob == NK)      cat = (c == NK) ? 5 : 4;
                else if (c == NK)     cat = 3;
                else if (qglob == c)  cat = 0;
                else if (qglob / Kc == c / Kc) cat = 1;
                else                  cat = 2;
                gte = tw[cat];
            }
            sS[r * 512 + c] *= gte * inv;
        }
    }
    __syncthreads();

    float oacc[2][4] = {};
    for (int t = 0; t < SP; t++) {
        int k0 = t * KT;
        for (int i = tid; i < KT * 16; i += 256) {
            int kr = i >> 4, n4 = (i & 15) * 4;
            float4 vv = make_float4(0.f, 0.f, 0.f, 0.f);
            if (k0 + kr < S)
                vv = *(const float4*)(V + ((size_t)(b * S + k0 + kr)) * DMODEL + h * DK + n4);
            *(float4*)&sKV[kr * 64 + n4] = vv;
        }
        __syncthreads();

        #pragma unroll 8
        for (int k = 0; k < KT; k++) {
            float p0 = sS[(qg * 2) * 512 + k0 + k];
            float p1 = sS[(qg * 2 + 1) * 512 + k0 + k];
            #pragma unroll
            for (int j = 0; j < 4; j++) {
                float vv = sKV[k * 64 + kg * 4 + j];
                oacc[0][j] = fmaf(p0, vv, oacc[0][j]);
                oacc[1][j] = fmaf(p1, vv, oacc[1][j]);
            }
        }
        __syncthreads();
    }

    #pragma unroll
    for (int i = 0; i < 2; i++) {
        int qglob = q0 + qg * 2 + i;
        if (qglob >= S) continue;
        #pragma unroll
        for (int j = 0; j < 4; j++)
            O[((size_t)(b * S + qglob)) * DMODEL + h * DK + kg * 4 + j] = oacc[i][j];
    }
}

// ---------------------------------------------------------------------------
extern "C" void kernel_launch(void* const* d_in, const int* in_sizes, int n_in,
                              void* d_out, int out_size) {
    const float* samples  = (const float*)d_in[0];
    const float* Wq       = (const float*)d_in[1];
    const float* Wk       = (const float*)d_in[2];
    const float* Wv       = (const float*)d_in[3];
    const float* attn_w   = (const float*)d_in[4];
    const float* mha_fc_w = (const float*)d_in[5];
    const float* mha_fc_b = (const float*)d_in[6];
    const float* mha_ln_g = (const float*)d_in[7];
    const float* mha_ln_b = (const float*)d_in[8];
    const float* d_fc1_w  = (const float*)d_in[9];
    const float* d_fc1_b  = (const float*)d_in[10];
    const float* d_fc2_w  = (const float*)d_in[11];
    const float* d_fc2_b  = (const float*)d_in[12];
    const float* d_ln_g   = (const float*)d_in[13];
    const float* d_ln_b   = (const float*)d_in[14];
    const float* out_fc_w = (const float*)d_in[15];
    const float* out_fc_b = (const float*)d_in[16];
    const float* out_ln_g = (const float*)d_in[17];
    const float* out_ln_b = (const float*)d_in[18];
    const int*   Kptr     = (const int*)d_in[20];

    const int S = in_sizes[0] / (BATCH * DMODEL);

    float* base = nullptr;
    cudaGetSymbolAddress((void**)&base, g_scratch);
    float* x  = base + 0 * CHUNK;
    float* q  = base + 1 * CHUNK;
    float* k  = base + 2 * CHUNK;
    float* v  = base + 3 * CHUNK;
    float* ao = base + 4 * CHUNK;

    __nv_bfloat16* wsp = nullptr;
    cudaGetSymbolAddress((void**)&wsp, g_wsplit);

    const int ATTN_SMEM = (QT * 64 + 64 * 64 + QT * 512) * 4;
    cudaFuncSetAttribute(attn_kernel, cudaFuncAttributeMaxDynamicSharedMemorySize, ATTN_SMEM);
    cudaFuncSetAttribute(gemm_tc, cudaFuncAttributeMaxDynamicSharedMemorySize, GEMM_DYN);

    WP wp;
    wp.p[0] = Wq;        wp.p[1] = Wq + 65536;
    wp.p[2] = Wk;        wp.p[3] = Wk + 65536;
    wp.p[4] = Wv;        wp.p[5] = Wv + 65536;
    wp.p[6] = mha_fc_w;  wp.p[7] = mha_fc_w + 65536;
    wp.p[8] = d_fc1_w;   wp.p[9] = d_fc1_w + 65536;
    wp.p[10] = d_fc2_w;  wp.p[11] = d_fc2_w + 65536;
    wp.p[12] = out_fc_w;
    prep_w<<<dim3(64, 13), 256>>>(wp, wsp);

    dim3 ga((S + QT - 1) / QT, NHEAD, BATCH);
    const int GR = S;   // (128*S)/128 row-tiles

    for (int l = 0; l < 2; l++) {
        const float* xin = (l == 0) ? samples : x;
        gemm_tc<<<GR, 256, GEMM_DYN>>>(xin, wsp + (size_t)(0 + l) * 131072,
                                       nullptr, nullptr, nullptr, nullptr, q, 0);
        gemm_tc<<<GR, 256, GEMM_DYN>>>(xin, wsp + (size_t)(2 + l) * 131072,
                                       nullptr, nullptr, nullptr, nullptr, k, 0);
        gemm_tc<<<GR, 256, GEMM_DYN>>>(xin, wsp + (size_t)(4 + l) * 131072,
                                       nullptr, nullptr, nullptr, nullptr, v, 0);
        attn_kernel<<<ga, 256, ATTN_SMEM>>>(q, k, v, attn_w + l * 24, Kptr, ao, S);
        gemm_tc<<<GR, 256, GEMM_DYN>>>(ao, wsp + (size_t)(6 + l) * 131072,
                                       mha_fc_b + l * 256, xin,
                                       mha_ln_g + l * 256, mha_ln_b + l * 256, x, 0);
        gemm_tc<<<GR, 256, GEMM_DYN>>>(x, wsp + (size_t)(8 + l) * 131072,
                                       d_fc1_b + l * 256, nullptr, nullptr, nullptr, q, 1);
        gemm_tc<<<GR, 256, GEMM_DYN>>>(q, wsp + (size_t)(10 + l) * 131072,
                                       d_fc2_b + l * 256, x,
                                       d_ln_g + l * 256, d_ln_b + l * 256, x, 0);
    }
    gemm_tc<<<GR, 256, GEMM_DYN>>>(x, wsp + (size_t)12 * 131072,
                                   out_fc_b, samples, out_ln_g, out_ln_b,
                                   (float*)d_out, 0);
}